// round 15
// baseline (speedup 1.0000x reference)
#include <cuda_runtime.h>
#include <cuda_fp16.h>
#include <cstdint>
#include <cstddef>

#define BATCH 64
#define NTOK  197
#define HW    1024
#define IMGW  32
#define KS    11
#define PADR  5
#define ALD   256   // padded token dim (j) for alpha
#define AVK   224   // ceil(197/32)*32 — AV K extent
#define CONV_NB 4   // images per conv CTA

// ---------------- scratch (static device globals; no allocs allowed) --------
__device__ __half g_qh[(size_t)BATCH * NTOK * HW];
__device__ __half g_kh[(size_t)BATCH * NTOK * HW];
__device__ __half g_vh[(size_t)BATCH * NTOK * HW];   // V hi [b][j][s]
__device__ __half g_ah[(size_t)BATCH * NTOK * ALD];  // softmax(alpha)

// ---------------- helpers ----------------------------------------------------
__device__ __forceinline__ uint32_t smem_u32(const void* p) {
    uint32_t a;
    asm("{ .reg .u64 t; cvta.to.shared.u64 t, %1; cvt.u32.u64 %0, t; }"
        : "=r"(a) : "l"(p));
    return a;
}
#define SWZ64(o) ((o) ^ (((o) >> 3) & 0x30))
#define SWZ256(o) ((o) ^ ((((o) >> 8) & 7) << 4))

__device__ __forceinline__ uint32_t lds32(uint32_t addr) {
    uint32_t v;
    asm volatile("ld.shared.b32 %0, [%1];" : "=r"(v) : "r"(addr));
    return v;
}
__device__ __forceinline__ void ldsm4(uint32_t* r, uint32_t addr) {
    asm volatile("ldmatrix.sync.aligned.m8n8.x4.shared.b16 {%0,%1,%2,%3}, [%4];"
                 : "=r"(r[0]), "=r"(r[1]), "=r"(r[2]), "=r"(r[3]) : "r"(addr));
}
__device__ __forceinline__ void ldsm4t(uint32_t* r, uint32_t addr) {
    asm volatile("ldmatrix.sync.aligned.m8n8.x4.trans.shared.b16 {%0,%1,%2,%3}, [%4];"
                 : "=r"(r[0]), "=r"(r[1]), "=r"(r[2]), "=r"(r[3]) : "r"(addr));
}
__device__ __forceinline__ void mma16816(float* d, const uint32_t* a,
                                         uint32_t b0, uint32_t b1) {
    asm volatile(
        "mma.sync.aligned.m16n8k16.row.col.f32.f16.f16.f32 "
        "{%0,%1,%2,%3}, {%4,%5,%6,%7}, {%8,%9}, {%0,%1,%2,%3};"
        : "+f"(d[0]), "+f"(d[1]), "+f"(d[2]), "+f"(d[3])
        : "r"(a[0]), "r"(a[1]), "r"(a[2]), "r"(a[3]), "r"(b0), "r"(b1));
}
__device__ __forceinline__ void cp16(uint32_t dst, const void* src, bool valid) {
    asm volatile("cp.async.cg.shared.global [%0], [%1], 16, %2;"
                 :: "r"(dst), "l"(src), "r"(valid ? 16 : 0) : "memory");
}
#define CP_COMMIT() asm volatile("cp.async.commit_group;" ::: "memory")
#define CP_WAIT2()  asm volatile("cp.async.wait_group 2;" ::: "memory")

// ================== fused QK + softmax (unchanged) ===========================
#define FQ_STG  20480
#define FQ_SMEM (3 * FQ_STG + 1024)

__device__ __forceinline__ void fqk_issue(
    char* smem, int stage, const __half* Q, int qRows, const __half* K,
    int k0, bool kvalid)
{
    const int tid = threadIdx.x;
    const uint32_t sbase = smem_u32(smem) + stage * FQ_STG;
    {
        const int row = tid >> 2, c = tid & 3;
        cp16(sbase + SWZ64((uint32_t)(row * 64 + c * 16)),
             Q + (size_t)row * HW + k0 + c * 8, kvalid && (row < qRows));
    }
#pragma unroll
    for (int g = 0; g < 4; g++) {
        const int idx = tid + g * 256;
        const int row = idx >> 2, c = idx & 3;
        cp16(sbase + 4096 + SWZ64((uint32_t)(row * 64 + c * 16)),
             K + (size_t)row * HW + k0 + c * 8, kvalid && (row < NTOK));
    }
}

__device__ __forceinline__ void fqk_compute(char* smem, int stage,
                                            float acc[2][8][4])
{
    const int tid = threadIdx.x, lane = tid & 31, wid = tid >> 5;
    const int wm = wid >> 2, wn = wid & 3;
    const uint32_t sbase = smem_u32(smem) + stage * FQ_STG;

#pragma unroll
    for (int k16 = 0; k16 < 2; k16++) {
        const int kc = k16 * 2 + (lane >> 4);
        uint32_t ah[2][4];
#pragma unroll
        for (int mt = 0; mt < 2; mt++) {
            const int row = wm * 32 + mt * 16 + (lane & 15);
            ldsm4(ah[mt], sbase + SWZ64((uint32_t)(row * 64 + kc * 16)));
        }
#pragma unroll
        for (int nt = 0; nt < 4; nt++) {
            const int row = wn * 64 + nt * 16 + (lane & 15);
            uint32_t bh[4];
            ldsm4(bh, sbase + 4096 + SWZ64((uint32_t)(row * 64 + kc * 16)));
#pragma unroll
            for (int mt = 0; mt < 2; mt++)
#pragma unroll
                for (int h = 0; h < 2; h++)
                    mma16816(acc[mt][nt * 2 + h], ah[mt], bh[h], bh[h + 2]);
        }
    }
}

__global__ void __launch_bounds__(256) qk_softmax_kernel()
{
    extern __shared__ __align__(1024) char smem[];
    const int b  = blockIdx.y;
    const int i0 = blockIdx.x * 64;
    const int tid = threadIdx.x, lane = tid & 31, wid = tid >> 5;
    const int wm = wid >> 2, wn = wid & 3;
    float* red = (float*)(smem + 3 * FQ_STG);   // [64][4]

    const size_t ob = (size_t)b * NTOK * HW;
    const __half* Q = g_qh + ob + (size_t)i0 * HW;
    const __half* K = g_kh + ob;

    float acc[2][8][4] = {};
    const int nk = HW >> 5;

#pragma unroll
    for (int s = 0; s < 3; s++) {
        fqk_issue(smem, s, Q, NTOK - i0, K, s * 32, s < nk);
        CP_COMMIT();
    }
    for (int k = 0; k < nk; k++) {
        const int st = k % 3;
        CP_WAIT2();
        __syncthreads();
        fqk_compute(smem, st, acc);
        __syncthreads();
        const int kn = k + 3;
        fqk_issue(smem, st, Q, NTOK - i0, K, kn * 32, kn < nk);
        CP_COMMIT();
    }

    const float scale = 1.0f / 32.0f;

#pragma unroll
    for (int mt = 0; mt < 2; mt++)
#pragma unroll
        for (int nb = 0; nb < 8; nb++)
#pragma unroll
            for (int d = 0; d < 4; d++) {
                const int col = wn * 64 + (nb >> 1) * 16 + (nb & 1) * 8 +
                                (lane & 3) * 2 + (d & 1);
                if (col >= NTOK) acc[mt][nb][d] = -1e30f;
            }

    float mrow[2][2];
#pragma unroll
    for (int mt = 0; mt < 2; mt++)
#pragma unroll
        for (int rr = 0; rr < 2; rr++) {
            float mx = -1e30f;
#pragma unroll
            for (int nb = 0; nb < 8; nb++) {
                mx = fmaxf(mx, acc[mt][nb][rr * 2 + 0]);
                mx = fmaxf(mx, acc[mt][nb][rr * 2 + 1]);
            }
            mx = fmaxf(mx, __shfl_xor_sync(0xFFFFFFFF, mx, 1));
            mx = fmaxf(mx, __shfl_xor_sync(0xFFFFFFFF, mx, 2));
            if ((lane & 3) == 0) {
                const int rowl = wm * 32 + mt * 16 + rr * 8 + (lane >> 2);
                red[rowl * 4 + wn] = mx;
            }
        }
    __syncthreads();
#pragma unroll
    for (int mt = 0; mt < 2; mt++)
#pragma unroll
        for (int rr = 0; rr < 2; rr++) {
            const int rowl = wm * 32 + mt * 16 + rr * 8 + (lane >> 2);
            mrow[mt][rr] = fmaxf(fmaxf(red[rowl * 4 + 0], red[rowl * 4 + 1]),
                                 fmaxf(red[rowl * 4 + 2], red[rowl * 4 + 3]));
        }
    __syncthreads();

    float inv[2][2];
#pragma unroll
    for (int mt = 0; mt < 2; mt++)
#pragma unroll
        for (int rr = 0; rr < 2; rr++) {
            float sm = 0.0f;
#pragma unroll
            for (int nb = 0; nb < 8; nb++)
#pragma unroll
                for (int c = 0; c < 2; c++) {
                    float e = expf((acc[mt][nb][rr * 2 + c] - mrow[mt][rr]) * scale);
                    acc[mt][nb][rr * 2 + c] = e;
                    sm += e;
                }
            sm += __shfl_xor_sync(0xFFFFFFFF, sm, 1);
            sm += __shfl_xor_sync(0xFFFFFFFF, sm, 2);
            if ((lane & 3) == 0) {
                const int rowl = wm * 32 + mt * 16 + rr * 8 + (lane >> 2);
                red[rowl * 4 + wn] = sm;
            }
        }
    __syncthreads();
#pragma unroll
    for (int mt = 0; mt < 2; mt++)
#pragma unroll
        for (int rr = 0; rr < 2; rr++) {
            const int rowl = wm * 32 + mt * 16 + rr * 8 + (lane >> 2);
            const float tot = red[rowl * 4 + 0] + red[rowl * 4 + 1] +
                              red[rowl * 4 + 2] + red[rowl * 4 + 3];
            inv[mt][rr] = 1.0f / tot;
        }

#pragma unroll
    for (int mt = 0; mt < 2; mt++)
#pragma unroll
        for (int rr = 0; rr < 2; rr++) {
            const int rowg = i0 + wm * 32 + mt * 16 + rr * 8 + (lane >> 2);
            if (rowg >= NTOK) continue;
            __half* arow = &g_ah[((size_t)b * NTOK + rowg) * ALD];
#pragma unroll
            for (int nb = 0; nb < 8; nb++) {
                const int col = wn * 64 + (nb >> 1) * 16 + (nb & 1) * 8 +
                                (lane & 3) * 2;
                __half2 h;
                h.x = __float2half_rn(acc[mt][nb][rr * 2 + 0] * inv[mt][rr]);
                h.y = __float2half_rn(acc[mt][nb][rr * 2 + 1] * inv[mt][rr]);
                *(__half2*)&arow[col] = h;
            }
        }
}

// ================== AV pipelined GEMM (1-term: A * Vh) =======================
#define STG_AV 16384
#define SMEM_AV (3 * STG_AV)

__device__ __forceinline__ void av_issue(
    char* smem, int stage,
    const __half* Ah, int lda, int aRows,
    const __half* Vh, int ldv, int s0,
    int k0, bool kvalid)
{
    const int tid = threadIdx.x;
    const uint32_t sbase = smem_u32(smem) + stage * STG_AV;
#pragma unroll
    for (int g = 0; g < 2; g++) {
        const int idx = tid + g * 256;
        const int row = idx >> 2, c = idx & 3;
        const uint32_t sw = SWZ64((uint32_t)(row * 64 + c * 16));
        cp16(sbase + sw, Ah + (size_t)row * lda + k0 + c * 8,
             kvalid && (row < aRows));
    }
#pragma unroll
    for (int g = 0; g < 2; g++) {
        const int idx = tid + g * 256;
        const int row = idx >> 4, c = idx & 15;
        const uint32_t sw = SWZ256((uint32_t)(row * 256 + c * 16));
        const int j = k0 + row;
        cp16(sbase + 8192 + sw, Vh + (size_t)j * ldv + s0 + c * 8, j < NTOK);
    }
}

__device__ __forceinline__ void av_compute(char* smem, int stage,
                                           float acc[2][8][4])
{
    const int tid = threadIdx.x, lane = tid & 31, wid = tid >> 5;
    const int wm = wid >> 1, wn = wid & 1;
    const uint32_t sbase = smem_u32(smem) + stage * STG_AV;

#pragma unroll
    for (int k16 = 0; k16 < 2; k16++) {
        const int kc = k16 * 2 + (lane >> 4);
        uint32_t ah[2][4];
#pragma unroll
        for (int mt = 0; mt < 2; mt++) {
            const int row = wm * 32 + mt * 16 + (lane & 15);
            ldsm4(ah[mt], sbase + SWZ64((uint32_t)(row * 64 + kc * 16)));
        }
        const int krow = k16 * 16 + (lane & 15);
#pragma unroll
        for (int nt = 0; nt < 4; nt++) {
            const uint32_t nb = (uint32_t)(wn * 128 + nt * 32 + (lane >> 4) * 16);
            const uint32_t off = SWZ256((uint32_t)(krow * 256) + nb);
            uint32_t bh[4];
            ldsm4t(bh, sbase + 8192 + off);
#pragma unroll
            for (int mt = 0; mt < 2; mt++)
#pragma unroll
                for (int h = 0; h < 2; h++)
                    mma16816(acc[mt][nt * 2 + h], ah[mt],
                             bh[h * 2], bh[h * 2 + 1]);
        }
    }
}

__device__ __forceinline__ void run_av(
    const __half* __restrict__ Ah, int lda, int aRows,
    const __half* __restrict__ Vh, int ldv, int s0,
    int kTotal, char* smem, float acc[2][8][4])
{
    const int nk = kTotal >> 5;
#pragma unroll
    for (int s = 0; s < 3; s++) {
        av_issue(smem, s, Ah, lda, aRows, Vh, ldv, s0, s * 32, s < nk);
        CP_COMMIT();
    }
    for (int k = 0; k < nk; k++) {
        const int st = k % 3;
        CP_WAIT2();
        __syncthreads();
        av_compute(smem, st, acc);
        __syncthreads();
        const int kn = k + 3;
        av_issue(smem, st, Ah, lda, aRows, Vh, ldv, s0, kn * 32, kn < nk);
        CP_COMMIT();
    }
}

// ---------------- 1) depthwise 11x11 conv via tensor cores, 4 images/CTA ----
#define PIW 48                      // padded row stride (halves)
#define PIN (42 * PIW)              // 2016 halves per copy

__global__ void __launch_bounds__(256) dwconv_tc_kernel(
    const float* __restrict__ x,
    const float* __restrict__ Wq,
    const float* __restrict__ Wk,
    const float* __restrict__ Wv)
{
    const int ch = blockIdx.x;
    const int b0 = blockIdx.y * CONV_NB;
    const int tid = threadIdx.x, lane = tid & 31, wid = tid >> 5;

    __shared__ __align__(16) __half sE[PIN];
    __shared__ __align__(16) __half sO[PIN];
    __shared__ __align__(16) __half wsm[11 * 8 * 16];   // [ky][n][kx]

    // one-time zero (pad regions persist across images)
    {
        uint32_t* zE = (uint32_t*)sE;
        uint32_t* zO = (uint32_t*)sO;
        for (int i = tid; i < PIN / 2; i += 256) { zE[i] = 0; zO[i] = 0; }
        uint32_t* zw = (uint32_t*)wsm;
        for (int i = tid; i < 11 * 8 * 16 / 2; i += 256) zw[i] = 0;
    }
    __syncthreads();

    // one-time weights -> wsm[ky][n][kx]
    if (tid < 176) {
        const int ky = tid >> 4, kx = tid & 15;
        if (kx < KS) {
            const int wi = ch * KS * KS + ky * KS + kx;
            wsm[(ky * 8 + 0) * 16 + kx] = __float2half_rn(Wq[wi]);
            wsm[(ky * 8 + 1) * 16 + kx] = __float2half_rn(Wk[wi]);
            wsm[(ky * 8 + 2) * 16 + kx] = __float2half_rn(Wv[wi]);
        }
    }
    __syncthreads();

    const int g = lane >> 2, tig = lane & 3;
    const uint32_t baseE = smem_u32(sE), baseO = smem_u32(sO);
    const uint32_t wbase = smem_u32(wsm);

    // one-time B-fragment hoist
    uint32_t b0r[11], b1r[11];
#pragma unroll
    for (int ky = 0; ky < 11; ky++) {
        const uint32_t wo = wbase + (uint32_t)(((ky * 8 + g) * 16 + 2 * tig) * 2);
        b0r[ky] = lds32(wo);
        b1r[ky] = lds32(wo + 16);
    }

    // image pixel block for this thread: 4 consecutive px in one row
    const int pr = tid >> 3;           // image row 0..31
    const int pc = (tid & 7) << 2;     // col 0,4..28

    float4 cur = *(const float4*)
        (x + ((size_t)b0 * NTOK + ch) * HW + pr * IMGW + pc);

    for (int bi = 0; bi < CONV_NB; bi++) {
        // store current image into both parity copies
        {
            const int rp = pr + PADR, cp = pc + PADR;
            const __half h0 = __float2half_rn(cur.x);
            const __half h1 = __float2half_rn(cur.y);
            const __half h2 = __float2half_rn(cur.z);
            const __half h3 = __float2half_rn(cur.w);
            __half* e = &sE[rp * PIW + cp];
            e[0] = h0; e[1] = h1; e[2] = h2; e[3] = h3;
            __half* o = &sO[rp * PIW + cp - 1];
            o[0] = h0; o[1] = h1; o[2] = h2; o[3] = h3;
        }
        // prefetch next image while computing
        float4 nxt;
        if (bi + 1 < CONV_NB)
            nxt = *(const float4*)
                (x + ((size_t)(b0 + bi + 1) * NTOK + ch) * HW + pr * IMGW + pc);
        __syncthreads();

        const size_t gb = ((size_t)(b0 + bi) * NTOK + ch) * HW;

#pragma unroll
        for (int tt = 0; tt < 8; tt++) {
            const int tile = wid * 8 + tt;
            const int p0 = tile * 16;
            const int r0 = tile >> 1;
            const int colbase = (tile & 1) * 16;

            const int cc  = colbase + g;
            const int par = cc & 1;
            const uint32_t bsel = par ? baseO : baseE;
            const uint32_t a0off =
                bsel + (uint32_t)((r0 * PIW + cc + 2 * tig - par) * 2);

            float acc[4] = {0.0f, 0.0f, 0.0f, 0.0f};
#pragma unroll
            for (int ky = 0; ky < 11; ky++) {
                const uint32_t ao = a0off + (uint32_t)(ky * (PIW * 2));
                const uint32_t w0 = lds32(ao);
                const uint32_t w1 = lds32(ao + 16);
                const uint32_t w2 = lds32(ao + 32);
                const uint32_t a[4] = {w0, w1, w1, w2};
                mma16816(acc, a, b0r[ky], b1r[ky]);
            }

            const int p = p0 + g;
            if (tig == 0) {
                g_qh[gb + p]     = __float2half_rn(acc[0]);
                g_kh[gb + p]     = __float2half_rn(acc[1]);
                g_qh[gb + p + 8] = __float2half_rn(acc[2]);
                g_kh[gb + p + 8] = __float2half_rn(acc[3]);
            } else if (tig == 1) {
                g_vh[gb + p]     = __float2half_rn(acc[0]);
                g_vh[gb + p + 8] = __float2half_rn(acc[2]);
            }
        }
        __syncthreads();
        cur = nxt;
    }
}

// ---------------- out = alpha V via mma.sync (trans-B, 1-term) --------------
__global__ void __launch_bounds__(256) av_mma_kernel(float* __restrict__ out)
{
    extern __shared__ __align__(1024) char smem[];
    const int b  = blockIdx.z;
    const int i0 = blockIdx.y * 128;
    const int s0 = blockIdx.x * 128;
    const int tid = threadIdx.x, lane = tid & 31, wid = tid >> 5;
    const int wm = wid >> 1, wn = wid & 1;

    float acc[2][8][4] = {};
    const size_t ab = (size_t)b * NTOK * ALD;
    const size_t vb = (size_t)b * NTOK * HW;
    run_av(g_ah + ab + (size_t)i0 * ALD, ALD, NTOK - i0,
           g_vh + vb, HW, s0, AVK, smem, acc);

#pragma unroll
    for (int mt = 0; mt < 2; mt++)
#pragma unroll
        for (int nt = 0; nt < 4; nt++)
#pragma unroll
            for (int h = 0; h < 2; h++) {
                const float* d = acc[mt][nt * 2 + h];
                const int col = s0 + wn * 64 + nt * 16 + h * 8 + (lane & 3) * 2;
                const int r0  = i0 + wm * 32 + mt * 16 + (lane >> 2);
                if (r0 < NTOK) {
                    float* p = &out[((size_t)b * NTOK + r0) * HW + col];
                    p[0] = d[0]; p[1] = d[1];
                }
                if (r0 + 8 < NTOK) {
                    float* p = &out[((size_t)b * NTOK + r0 + 8) * HW + col];
                    p[0] = d[2]; p[1] = d[3];
                }
            }
}

// ---------------- launch ----------------------------------------------------
extern "C" void kernel_launch(void* const* d_in, const int* in_sizes, int n_in,
                              void* d_out, int out_size)
{
    const float* x  = (const float*)d_in[0];
    const float* Wq = (const float*)d_in[1];
    const float* Wk = (const float*)d_in[2];
    const float* Wv = (const float*)d_in[3];
    float* out = (float*)d_out;

    cudaFuncSetAttribute(qk_softmax_kernel,
                         cudaFuncAttributeMaxDynamicSharedMemorySize, FQ_SMEM);
    cudaFuncSetAttribute(av_mma_kernel,
                         cudaFuncAttributeMaxDynamicSharedMemorySize, SMEM_AV);

    dim3 gConv(NTOK, BATCH / CONV_NB);
    dwconv_tc_kernel<<<gConv, 256>>>(x, Wq, Wk, Wv);

    dim3 gQK(4, BATCH);
    qk_softmax_kernel<<<gQK, 256, FQ_SMEM>>>();

    dim3 gAV(8, 2, BATCH);
    av_mma_kernel<<<gAV, 256, SMEM_AV>>>(out);
}

// round 17
// speedup vs baseline: 1.2412x; 1.2412x over previous
#include <cuda_runtime.h>
#include <cuda_fp16.h>
#include <cstdint>
#include <cstddef>

#define BATCH 64
#define NTOK  197
#define HW    1024
#define IMGW  32
#define KS    11
#define PADR  5
#define ALD   256   // padded token dim (j) for alpha
#define AVK   224   // ceil(197/32)*32 — AV K extent

// ---------------- scratch (static device globals; no allocs allowed) --------
__device__ __half g_qh[(size_t)BATCH * NTOK * HW];
__device__ __half g_kh[(size_t)BATCH * NTOK * HW];
__device__ __half g_vh[(size_t)BATCH * NTOK * HW];   // V hi [b][j][s]
__device__ __half g_ah[(size_t)BATCH * NTOK * ALD];  // softmax(alpha)

// ---------------- helpers ----------------------------------------------------
__device__ __forceinline__ uint32_t smem_u32(const void* p) {
    uint32_t a;
    asm("{ .reg .u64 t; cvta.to.shared.u64 t, %1; cvt.u32.u64 %0, t; }"
        : "=r"(a) : "l"(p));
    return a;
}
#define SWZ64(o) ((o) ^ (((o) >> 3) & 0x30))
#define SWZ256(o) ((o) ^ ((((o) >> 8) & 7) << 4))

__device__ __forceinline__ uint32_t lds32(uint32_t addr) {
    uint32_t v;
    asm volatile("ld.shared.b32 %0, [%1];" : "=r"(v) : "r"(addr));
    return v;
}
__device__ __forceinline__ void ldsm4(uint32_t* r, uint32_t addr) {
    asm volatile("ldmatrix.sync.aligned.m8n8.x4.shared.b16 {%0,%1,%2,%3}, [%4];"
                 : "=r"(r[0]), "=r"(r[1]), "=r"(r[2]), "=r"(r[3]) : "r"(addr));
}
__device__ __forceinline__ void ldsm4t(uint32_t* r, uint32_t addr) {
    asm volatile("ldmatrix.sync.aligned.m8n8.x4.trans.shared.b16 {%0,%1,%2,%3}, [%4];"
                 : "=r"(r[0]), "=r"(r[1]), "=r"(r[2]), "=r"(r[3]) : "r"(addr));
}
__device__ __forceinline__ void mma16816(float* d, const uint32_t* a,
                                         uint32_t b0, uint32_t b1) {
    asm volatile(
        "mma.sync.aligned.m16n8k16.row.col.f32.f16.f16.f32 "
        "{%0,%1,%2,%3}, {%4,%5,%6,%7}, {%8,%9}, {%0,%1,%2,%3};"
        : "+f"(d[0]), "+f"(d[1]), "+f"(d[2]), "+f"(d[3])
        : "r"(a[0]), "r"(a[1]), "r"(a[2]), "r"(a[3]), "r"(b0), "r"(b1));
}
__device__ __forceinline__ void cp16(uint32_t dst, const void* src, bool valid) {
    asm volatile("cp.async.cg.shared.global [%0], [%1], 16, %2;"
                 :: "r"(dst), "l"(src), "r"(valid ? 16 : 0) : "memory");
}
#define CP_COMMIT() asm volatile("cp.async.commit_group;" ::: "memory")
#define CP_WAIT2()  asm volatile("cp.async.wait_group 2;" ::: "memory")

// ================== fused QK + softmax (unchanged) ===========================
#define FQ_STG  20480
#define FQ_SMEM (3 * FQ_STG + 1024)

__device__ __forceinline__ void fqk_issue(
    char* smem, int stage, const __half* Q, int qRows, const __half* K,
    int k0, bool kvalid)
{
    const int tid = threadIdx.x;
    const uint32_t sbase = smem_u32(smem) + stage * FQ_STG;
    {
        const int row = tid >> 2, c = tid & 3;
        cp16(sbase + SWZ64((uint32_t)(row * 64 + c * 16)),
             Q + (size_t)row * HW + k0 + c * 8, kvalid && (row < qRows));
    }
#pragma unroll
    for (int g = 0; g < 4; g++) {
        const int idx = tid + g * 256;
        const int row = idx >> 2, c = idx & 3;
        cp16(sbase + 4096 + SWZ64((uint32_t)(row * 64 + c * 16)),
             K + (size_t)row * HW + k0 + c * 8, kvalid && (row < NTOK));
    }
}

__device__ __forceinline__ void fqk_compute(char* smem, int stage,
                                            float acc[2][8][4])
{
    const int tid = threadIdx.x, lane = tid & 31, wid = tid >> 5;
    const int wm = wid >> 2, wn = wid & 3;
    const uint32_t sbase = smem_u32(smem) + stage * FQ_STG;

#pragma unroll
    for (int k16 = 0; k16 < 2; k16++) {
        const int kc = k16 * 2 + (lane >> 4);
        uint32_t ah[2][4];
#pragma unroll
        for (int mt = 0; mt < 2; mt++) {
            const int row = wm * 32 + mt * 16 + (lane & 15);
            ldsm4(ah[mt], sbase + SWZ64((uint32_t)(row * 64 + kc * 16)));
        }
#pragma unroll
        for (int nt = 0; nt < 4; nt++) {
            const int row = wn * 64 + nt * 16 + (lane & 15);
            uint32_t bh[4];
            ldsm4(bh, sbase + 4096 + SWZ64((uint32_t)(row * 64 + kc * 16)));
#pragma unroll
            for (int mt = 0; mt < 2; mt++)
#pragma unroll
                for (int h = 0; h < 2; h++)
                    mma16816(acc[mt][nt * 2 + h], ah[mt], bh[h], bh[h + 2]);
        }
    }
}

__global__ void __launch_bounds__(256) qk_softmax_kernel()
{
    extern __shared__ __align__(1024) char smem[];
    const int b  = blockIdx.y;
    const int i0 = blockIdx.x * 64;
    const int tid = threadIdx.x, lane = tid & 31, wid = tid >> 5;
    const int wm = wid >> 2, wn = wid & 3;
    float* red = (float*)(smem + 3 * FQ_STG);   // [64][4]

    const size_t ob = (size_t)b * NTOK * HW;
    const __half* Q = g_qh + ob + (size_t)i0 * HW;
    const __half* K = g_kh + ob;

    float acc[2][8][4] = {};
    const int nk = HW >> 5;

#pragma unroll
    for (int s = 0; s < 3; s++) {
        fqk_issue(smem, s, Q, NTOK - i0, K, s * 32, s < nk);
        CP_COMMIT();
    }
    for (int k = 0; k < nk; k++) {
        const int st = k % 3;
        CP_WAIT2();
        __syncthreads();
        fqk_compute(smem, st, acc);
        __syncthreads();
        const int kn = k + 3;
        fqk_issue(smem, st, Q, NTOK - i0, K, kn * 32, kn < nk);
        CP_COMMIT();
    }

    const float scale = 1.0f / 32.0f;

#pragma unroll
    for (int mt = 0; mt < 2; mt++)
#pragma unroll
        for (int nb = 0; nb < 8; nb++)
#pragma unroll
            for (int d = 0; d < 4; d++) {
                const int col = wn * 64 + (nb >> 1) * 16 + (nb & 1) * 8 +
                                (lane & 3) * 2 + (d & 1);
                if (col >= NTOK) acc[mt][nb][d] = -1e30f;
            }

    float mrow[2][2];
#pragma unroll
    for (int mt = 0; mt < 2; mt++)
#pragma unroll
        for (int rr = 0; rr < 2; rr++) {
            float mx = -1e30f;
#pragma unroll
            for (int nb = 0; nb < 8; nb++) {
                mx = fmaxf(mx, acc[mt][nb][rr * 2 + 0]);
                mx = fmaxf(mx, acc[mt][nb][rr * 2 + 1]);
            }
            mx = fmaxf(mx, __shfl_xor_sync(0xFFFFFFFF, mx, 1));
            mx = fmaxf(mx, __shfl_xor_sync(0xFFFFFFFF, mx, 2));
            if ((lane & 3) == 0) {
                const int rowl = wm * 32 + mt * 16 + rr * 8 + (lane >> 2);
                red[rowl * 4 + wn] = mx;
            }
        }
    __syncthreads();
#pragma unroll
    for (int mt = 0; mt < 2; mt++)
#pragma unroll
        for (int rr = 0; rr < 2; rr++) {
            const int rowl = wm * 32 + mt * 16 + rr * 8 + (lane >> 2);
            mrow[mt][rr] = fmaxf(fmaxf(red[rowl * 4 + 0], red[rowl * 4 + 1]),
                                 fmaxf(red[rowl * 4 + 2], red[rowl * 4 + 3]));
        }
    __syncthreads();

    float inv[2][2];
#pragma unroll
    for (int mt = 0; mt < 2; mt++)
#pragma unroll
        for (int rr = 0; rr < 2; rr++) {
            float sm = 0.0f;
#pragma unroll
            for (int nb = 0; nb < 8; nb++)
#pragma unroll
                for (int c = 0; c < 2; c++) {
                    float e = expf((acc[mt][nb][rr * 2 + c] - mrow[mt][rr]) * scale);
                    acc[mt][nb][rr * 2 + c] = e;
                    sm += e;
                }
            sm += __shfl_xor_sync(0xFFFFFFFF, sm, 1);
            sm += __shfl_xor_sync(0xFFFFFFFF, sm, 2);
            if ((lane & 3) == 0) {
                const int rowl = wm * 32 + mt * 16 + rr * 8 + (lane >> 2);
                red[rowl * 4 + wn] = sm;
            }
        }
    __syncthreads();
#pragma unroll
    for (int mt = 0; mt < 2; mt++)
#pragma unroll
        for (int rr = 0; rr < 2; rr++) {
            const int rowl = wm * 32 + mt * 16 + rr * 8 + (lane >> 2);
            const float tot = red[rowl * 4 + 0] + red[rowl * 4 + 1] +
                              red[rowl * 4 + 2] + red[rowl * 4 + 3];
            inv[mt][rr] = 1.0f / tot;
        }

#pragma unroll
    for (int mt = 0; mt < 2; mt++)
#pragma unroll
        for (int rr = 0; rr < 2; rr++) {
            const int rowg = i0 + wm * 32 + mt * 16 + rr * 8 + (lane >> 2);
            if (rowg >= NTOK) continue;
            __half* arow = &g_ah[((size_t)b * NTOK + rowg) * ALD];
#pragma unroll
            for (int nb = 0; nb < 8; nb++) {
                const int col = wn * 64 + (nb >> 1) * 16 + (nb & 1) * 8 +
                                (lane & 3) * 2;
                __half2 h;
                h.x = __float2half_rn(acc[mt][nb][rr * 2 + 0] * inv[mt][rr]);
                h.y = __float2half_rn(acc[mt][nb][rr * 2 + 1] * inv[mt][rr]);
                *(__half2*)&arow[col] = h;
            }
        }
}

// ================== AV pipelined GEMM (1-term: A * Vh) =======================
#define STG_AV 16384
#define SMEM_AV (3 * STG_AV)

__device__ __forceinline__ void av_issue(
    char* smem, int stage,
    const __half* Ah, int lda, int aRows,
    const __half* Vh, int ldv, int s0,
    int k0, bool kvalid)
{
    const int tid = threadIdx.x;
    const uint32_t sbase = smem_u32(smem) + stage * STG_AV;
#pragma unroll
    for (int g = 0; g < 2; g++) {
        const int idx = tid + g * 256;
        const int row = idx >> 2, c = idx & 3;
        const uint32_t sw = SWZ64((uint32_t)(row * 64 + c * 16));
        cp16(sbase + sw, Ah + (size_t)row * lda + k0 + c * 8,
             kvalid && (row < aRows));
    }
#pragma unroll
    for (int g = 0; g < 2; g++) {
        const int idx = tid + g * 256;
        const int row = idx >> 4, c = idx & 15;
        const uint32_t sw = SWZ256((uint32_t)(row * 256 + c * 16));
        const int j = k0 + row;
        cp16(sbase + 8192 + sw, Vh + (size_t)j * ldv + s0 + c * 8, j < NTOK);
    }
}

__device__ __forceinline__ void av_compute(char* smem, int stage,
                                           float acc[2][8][4])
{
    const int tid = threadIdx.x, lane = tid & 31, wid = tid >> 5;
    const int wm = wid >> 1, wn = wid & 1;
    const uint32_t sbase = smem_u32(smem) + stage * STG_AV;

#pragma unroll
    for (int k16 = 0; k16 < 2; k16++) {
        const int kc = k16 * 2 + (lane >> 4);
        uint32_t ah[2][4];
#pragma unroll
        for (int mt = 0; mt < 2; mt++) {
            const int row = wm * 32 + mt * 16 + (lane & 15);
            ldsm4(ah[mt], sbase + SWZ64((uint32_t)(row * 64 + kc * 16)));
        }
        const int krow = k16 * 16 + (lane & 15);
#pragma unroll
        for (int nt = 0; nt < 4; nt++) {
            const uint32_t nb = (uint32_t)(wn * 128 + nt * 32 + (lane >> 4) * 16);
            const uint32_t off = SWZ256((uint32_t)(krow * 256) + nb);
            uint32_t bh[4];
            ldsm4t(bh, sbase + 8192 + off);
#pragma unroll
            for (int mt = 0; mt < 2; mt++)
#pragma unroll
                for (int h = 0; h < 2; h++)
                    mma16816(acc[mt][nt * 2 + h], ah[mt],
                             bh[h * 2], bh[h * 2 + 1]);
        }
    }
}

__device__ __forceinline__ void run_av(
    const __half* __restrict__ Ah, int lda, int aRows,
    const __half* __restrict__ Vh, int ldv, int s0,
    int kTotal, char* smem, float acc[2][8][4])
{
    const int nk = kTotal >> 5;
#pragma unroll
    for (int s = 0; s < 3; s++) {
        av_issue(smem, s, Ah, lda, aRows, Vh, ldv, s0, s * 32, s < nk);
        CP_COMMIT();
    }
    for (int k = 0; k < nk; k++) {
        const int st = k % 3;
        CP_WAIT2();
        __syncthreads();
        av_compute(smem, st, acc);
        __syncthreads();
        const int kn = k + 3;
        av_issue(smem, st, Ah, lda, aRows, Vh, ldv, s0, kn * 32, kn < nk);
        CP_COMMIT();
    }
}

// ---------------- 1) depthwise 11x11 conv via tensor cores (R14 form) -------
#define PIW 48                      // padded row stride (halves)
#define PIN (42 * PIW)              // 2016 halves per copy

__global__ void __launch_bounds__(256, 4) dwconv_tc_kernel(
    const float* __restrict__ x,
    const float* __restrict__ Wq,
    const float* __restrict__ Wk,
    const float* __restrict__ Wv)
{
    const int ch = blockIdx.x;
    const int b  = blockIdx.y;
    const int tid = threadIdx.x, lane = tid & 31, wid = tid >> 5;

    __shared__ __align__(16) __half sE[PIN];
    __shared__ __align__(16) __half sO[PIN];
    __shared__ __align__(16) __half wsm[11 * 8 * 16];   // [ky][n][kx]

    {
        uint32_t* zE = (uint32_t*)sE;
        uint32_t* zO = (uint32_t*)sO;
        for (int i = tid; i < PIN / 2; i += 256) { zE[i] = 0; zO[i] = 0; }
        uint32_t* zw = (uint32_t*)wsm;
        for (int i = tid; i < 11 * 8 * 16 / 2; i += 256) zw[i] = 0;
    }
    __syncthreads();

    if (tid < 176) {
        const int ky = tid >> 4, kx = tid & 15;
        if (kx < KS) {
            const int wi = ch * KS * KS + ky * KS + kx;
            wsm[(ky * 8 + 0) * 16 + kx] = __float2half_rn(Wq[wi]);
            wsm[(ky * 8 + 1) * 16 + kx] = __float2half_rn(Wk[wi]);
            wsm[(ky * 8 + 2) * 16 + kx] = __float2half_rn(Wv[wi]);
        }
    }
    const float* xim = x + ((size_t)b * NTOK + ch) * HW;
    for (int i = tid; i < HW; i += 256) {
        const int r = i >> 5, c = i & 31;
        const __half h = __float2half_rn(xim[i]);
        const int rp = r + PADR, cp = c + PADR;
        sE[rp * PIW + cp] = h;
        sO[rp * PIW + cp - 1] = h;
    }
    __syncthreads();

    const int g = lane >> 2, tig = lane & 3;
    const uint32_t baseE = smem_u32(sE), baseO = smem_u32(sO);
    const uint32_t wbase = smem_u32(wsm);

    uint32_t b0r[11], b1r[11];
#pragma unroll
    for (int ky = 0; ky < 11; ky++) {
        const uint32_t wo = wbase + (uint32_t)(((ky * 8 + g) * 16 + 2 * tig) * 2);
        b0r[ky] = lds32(wo);
        b1r[ky] = lds32(wo + 16);
    }

    const size_t gb = ((size_t)b * NTOK + ch) * HW;

#pragma unroll
    for (int tt = 0; tt < 8; tt++) {
        const int tile = wid * 8 + tt;        // 0..63
        const int p0 = tile * 16;
        const int r0 = tile >> 1;
        const int colbase = (tile & 1) * 16;

        const int cc  = colbase + g;
        const int par = cc & 1;
        const uint32_t bsel = par ? baseO : baseE;
        const uint32_t a0off = bsel + (uint32_t)((r0 * PIW + cc + 2 * tig - par) * 2);

        float acc[4] = {0.0f, 0.0f, 0.0f, 0.0f};
#pragma unroll
        for (int ky = 0; ky < 11; ky++) {
            const uint32_t ao = a0off + (uint32_t)(ky * (PIW * 2));
            const uint32_t w0 = lds32(ao);
            const uint32_t w1 = lds32(ao + 16);
            const uint32_t w2 = lds32(ao + 32);
            const uint32_t a[4] = {w0, w1, w1, w2};
            mma16816(acc, a, b0r[ky], b1r[ky]);
        }

        const int p = p0 + g;
        if (tig == 0) {
            g_qh[gb + p]     = __float2half_rn(acc[0]);
            g_kh[gb + p]     = __float2half_rn(acc[1]);
            g_qh[gb + p + 8] = __float2half_rn(acc[2]);
            g_kh[gb + p + 8] = __float2half_rn(acc[3]);
        } else if (tig == 1) {
            g_vh[gb + p]     = __float2half_rn(acc[0]);
            g_vh[gb + p + 8] = __float2half_rn(acc[2]);
        }
    }
}

// ---------------- out = alpha V via mma.sync (trans-B, 1-term) --------------
__global__ void __launch_bounds__(256) av_mma_kernel(float* __restrict__ out)
{
    extern __shared__ __align__(1024) char smem[];
    const int b  = blockIdx.z;
    const int i0 = blockIdx.y * 128;
    const int s0 = blockIdx.x * 128;
    const int tid = threadIdx.x, lane = tid & 31, wid = tid >> 5;
    const int wm = wid >> 1, wn = wid & 1;

    float acc[2][8][4] = {};
    const size_t ab = (size_t)b * NTOK * ALD;
    const size_t vb = (size_t)b * NTOK * HW;
    run_av(g_ah + ab + (size_t)i0 * ALD, ALD, NTOK - i0,
           g_vh + vb, HW, s0, AVK, smem, acc);

#pragma unroll
    for (int mt = 0; mt < 2; mt++)
#pragma unroll
        for (int nt = 0; nt < 4; nt++)
#pragma unroll
            for (int h = 0; h < 2; h++) {
                const float* d = acc[mt][nt * 2 + h];
                const int col = s0 + wn * 64 + nt * 16 + h * 8 + (lane & 3) * 2;
                const int r0  = i0 + wm * 32 + mt * 16 + (lane >> 2);
                if (r0 < NTOK) {
                    float* p = &out[((size_t)b * NTOK + r0) * HW + col];
                    p[0] = d[0]; p[1] = d[1];
                }
                if (r0 + 8 < NTOK) {
                    float* p = &out[((size_t)b * NTOK + r0 + 8) * HW + col];
                    p[0] = d[2]; p[1] = d[3];
                }
            }
}

// ---------------- launch ----------------------------------------------------
extern "C" void kernel_launch(void* const* d_in, const int* in_sizes, int n_in,
                              void* d_out, int out_size)
{
    const float* x  = (const float*)d_in[0];
    const float* Wq = (const float*)d_in[1];
    const float* Wk = (const float*)d_in[2];
    const float* Wv = (const float*)d_in[3];
    float* out = (float*)d_out;

    cudaFuncSetAttribute(qk_softmax_kernel,
                         cudaFuncAttributeMaxDynamicSharedMemorySize, FQ_SMEM);
    cudaFuncSetAttribute(av_mma_kernel,
                         cudaFuncAttributeMaxDynamicSharedMemorySize, SMEM_AV);

    dim3 gConv(NTOK, BATCH);
    dwconv_tc_kernel<<<gConv, 256>>>(x, Wq, Wk, Wv);

    dim3 gQK(4, BATCH);
    qk_softmax_kernel<<<gQK, 256, FQ_SMEM>>>();

    dim3 gAV(8, 2, BATCH);
    av_mma_kernel<<<gAV, 256, SMEM_AV>>>(out);
}